// round 4
// baseline (speedup 1.0000x reference)
#include <cuda_runtime.h>
#include <cuda_bf16.h>
#include <math.h>

// ---------------------------------------------------------------------------
// GritLM pooling: masked segment mean over tokens + L2 normalize per sequence.
// Inputs (metadata order):
//   d_in[0] : float32 hidden_states [TOTAL, D]
//   d_in[1] : int32   prompt_lens   [B]
//   d_in[2] : int32   instruction_lens [B]
// Output: float32 [B, D]
//
// Single fused kernel: masked partial sums (memory-wall bound) + in-kernel
// last-CTA reduction -> mean -> L2 normalize. Counters reset by consumers so
// repeated graph replays are correct.
// ---------------------------------------------------------------------------

#define TSPLIT 16
#define MAX_B  64
#define MAX_D  8192
#define MAX_NX 8          // max D/1024 column chunks

// Static device scratch (runtime allocs forbidden). Zero-initialized at load;
// counters are reset to 0 by their consumer at each use.
__device__ float g_part[(size_t)TSPLIT * MAX_B * MAX_D];
__device__ float g_ssq [(size_t)MAX_B * MAX_NX];
__device__ int   g_cnt1[(size_t)MAX_B * MAX_NX];
__device__ int   g_cnt2[(size_t)MAX_B];

__device__ __forceinline__ float4 ldcs4(const float* p) {
    return __ldcs((const float4*)p);
}

// ---------------------------------------------------------------------------
// grid: (ceil(D/1024), B, TSPLIT), block: 256 threads.
// Phase A (all CTAs): masked partial column sums, 8x row unroll (MLP=8).
// Phase B (last CTA per (b, chunk)): reduce TSPLIT partials -> mean chunk,
//         write unnormalized mean to out, chunk sum-of-squares.
// Phase C (last chunk per b): fixed-order ssq sum -> norm -> rescale row.
// ---------------------------------------------------------------------------
__global__ __launch_bounds__(256, 8)
void pool_fused_kernel(const float* __restrict__ hs,
                       const int* __restrict__ plen,
                       const int* __restrict__ ilen,
                       float* __restrict__ out,
                       int B, int D)
{
    const int x     = blockIdx.x;          // column chunk (1024 floats)
    const int b     = blockIdx.y;
    const int split = blockIdx.z;
    const int nx    = gridDim.x;
    const int c0    = x * 1024 + threadIdx.x * 4;

    // ---- Phase A: partial masked column sums --------------------------------
    long long start = 0;
    for (int i = 0; i < b; i++) start += (long long)plen[i];
    const int len  = plen[b];
    const int inst = ilen[b];

    const int chunk = (len + TSPLIT - 1) / TSPLIT;
    int r0 = split * chunk;
    int r1 = r0 + chunk; if (r1 > len) r1 = len;
    if (r0 < inst) r0 = inst;              // mask instruction tokens

    float4 acc0 = make_float4(0.f, 0.f, 0.f, 0.f);
    float4 acc1 = make_float4(0.f, 0.f, 0.f, 0.f);

    if (c0 < D && r0 < r1) {
        const float* base = hs + (start + (long long)r0) * (long long)D + c0;
        const long long stride = D;
        int r = r0;
        for (; r + 7 < r1; r += 8) {       // MLP=8 independent LDG.128
            float4 v0 = ldcs4(base);
            float4 v1 = ldcs4(base + stride);
            float4 v2 = ldcs4(base + 2 * stride);
            float4 v3 = ldcs4(base + 3 * stride);
            float4 v4 = ldcs4(base + 4 * stride);
            float4 v5 = ldcs4(base + 5 * stride);
            float4 v6 = ldcs4(base + 6 * stride);
            float4 v7 = ldcs4(base + 7 * stride);
            acc0.x += v0.x + v1.x + v2.x + v3.x;
            acc0.y += v0.y + v1.y + v2.y + v3.y;
            acc0.z += v0.z + v1.z + v2.z + v3.z;
            acc0.w += v0.w + v1.w + v2.w + v3.w;
            acc1.x += v4.x + v5.x + v6.x + v7.x;
            acc1.y += v4.y + v5.y + v6.y + v7.y;
            acc1.z += v4.z + v5.z + v6.z + v7.z;
            acc1.w += v4.w + v5.w + v6.w + v7.w;
            base += 8 * stride;
        }
        for (; r < r1; r++) {
            float4 v = ldcs4(base);
            acc0.x += v.x; acc0.y += v.y; acc0.z += v.z; acc0.w += v.w;
            base += stride;
        }
    }

    if (c0 < D) {
        acc0.x += acc1.x; acc0.y += acc1.y; acc0.z += acc1.z; acc0.w += acc1.w;
        *(float4*)&g_part[((size_t)split * B + b) * (size_t)D + c0] = acc0;
    }

    // ---- handoff: last CTA of the TSPLIT group becomes the chunk reducer ---
    __threadfence();
    __syncthreads();
    __shared__ int s_role;
    if (threadIdx.x == 0) {
        int v = atomicAdd(&g_cnt1[b * nx + x], 1);
        s_role = (v == TSPLIT - 1);
    }
    __syncthreads();
    if (!s_role) return;

    // ---- Phase B: chunk reduction -> mean -> partial ssq --------------------
    if (threadIdx.x == 0) g_cnt1[b * nx + x] = 0;   // reset for next replay
    __threadfence();

    float4 s = make_float4(0.f, 0.f, 0.f, 0.f);
    if (c0 < D) {
#pragma unroll
        for (int t = 0; t < TSPLIT; t++) {
            const float4 v = *(const float4*)&g_part[((size_t)t * B + b) * (size_t)D + c0];
            s.x += v.x; s.y += v.y; s.z += v.z; s.w += v.w;
        }
        const float inv = 1.0f / (float)(len - inst);
        s.x *= inv; s.y *= inv; s.z *= inv; s.w *= inv;
        *(float4*)(out + (size_t)b * D + c0) = s;   // unnormalized mean
    }

    float ss = s.x * s.x + s.y * s.y + s.z * s.z + s.w * s.w;
    __shared__ float sm[32];
    for (int off = 16; off > 0; off >>= 1)
        ss += __shfl_down_sync(0xFFFFFFFFu, ss, off);
    const int lane = threadIdx.x & 31, wid = threadIdx.x >> 5;
    if (lane == 0) sm[wid] = ss;
    __syncthreads();
    if (wid == 0) {
        float v = (lane < 8) ? sm[lane] : 0.f;
        for (int off = 4; off > 0; off >>= 1)
            v += __shfl_down_sync(0xFFFFFFFFu, v, off);
        if (lane == 0) sm[0] = v;
    }
    __syncthreads();

    __shared__ int s_role2;
    if (threadIdx.x == 0) {
        g_ssq[b * nx + x] = sm[0];
        __threadfence();
        int v2 = atomicAdd(&g_cnt2[b], 1);
        s_role2 = (v2 == nx - 1);
    }
    __syncthreads();
    if (!s_role2) return;

    // ---- Phase C: final norm + rescale of row b -----------------------------
    if (threadIdx.x == 0) g_cnt2[b] = 0;            // reset for next replay
    __threadfence();

    float tot = 0.f;
    for (int xi = 0; xi < nx; xi++)                  // fixed order: deterministic
        tot += g_ssq[b * nx + xi];
    const float inv_n = 1.0f / fmaxf(sqrtf(tot), 1e-12f);

    for (int xi = 0; xi < nx; xi++) {
        const int c = xi * 1024 + threadIdx.x * 4;
        if (c < D) {
            float4 v = *(const float4*)(out + (size_t)b * D + c);
            v.x *= inv_n; v.y *= inv_n; v.z *= inv_n; v.w *= inv_n;
            *(float4*)(out + (size_t)b * D + c) = v;
        }
    }
}

// ---------------------------------------------------------------------------
extern "C" void kernel_launch(void* const* d_in, const int* in_sizes, int n_in,
                              void* d_out, int out_size)
{
    const float* hs   = (const float*)d_in[0];
    const int*   plen = (const int*)d_in[1];
    const int*   ilen = (const int*)d_in[2];
    float*       out  = (float*)d_out;

    const int B = in_sizes[1];
    const int D = out_size / B;   // 4096

    dim3 grid((D + 1023) / 1024, B, TSPLIT);
    pool_fused_kernel<<<grid, 256>>>(hs, plen, ilen, out, B, D);
}

// round 5
// speedup vs baseline: 1.0246x; 1.0246x over previous
#include <cuda_runtime.h>
#include <cuda_bf16.h>
#include <math.h>

// ---------------------------------------------------------------------------
// GritLM pooling: masked segment mean over tokens + L2 normalize per sequence.
// Inputs (metadata order):
//   d_in[0] : float32 hidden_states [TOTAL, D]
//   d_in[1] : int32   prompt_lens   [B]
//   d_in[2] : int32   instruction_lens [B]
// Output: float32 [B, D]
//
// Stage 1: masked partial column sums (memory-wall bound, ~6.3 TB/s cap).
// Stage 2: fused reduce + mean + L2 normalize, launched with PDL so its
//          prologue overlaps stage 1's tail.
// ---------------------------------------------------------------------------

#define TSPLIT 16
#define MAX_B 64
#define MAX_D 8192
// Partial-sum scratch (static device allocation; runtime allocs forbidden).
__device__ float g_part[(size_t)TSPLIT * MAX_B * MAX_D];

__device__ __forceinline__ float4 ldcs4(const float* p) {
    return __ldcs((const float4*)p);
}

// ---------------------------------------------------------------------------
// Kernel 1: partial masked column sums.
// grid: (ceil(D/1024), B, TSPLIT), block: 256 threads.
// 8x row unroll -> 8 outstanding LDG.128 per thread (deep MLP).
// ---------------------------------------------------------------------------
__global__ __launch_bounds__(256, 8)
void pool_partial_kernel(const float* __restrict__ hs,
                         const int* __restrict__ plen,
                         const int* __restrict__ ilen,
                         int B, int D)
{
    const int b     = blockIdx.y;
    const int split = blockIdx.z;
    const int c0    = blockIdx.x * 1024 + threadIdx.x * 4;

    long long start = 0;
    for (int i = 0; i < b; i++) start += (long long)plen[i];
    const int len  = plen[b];
    const int inst = ilen[b];

    const int chunk = (len + TSPLIT - 1) / TSPLIT;
    int r0 = split * chunk;
    int r1 = r0 + chunk; if (r1 > len) r1 = len;
    if (r0 < inst) r0 = inst;        // mask instruction tokens

    float4 acc0 = make_float4(0.f, 0.f, 0.f, 0.f);
    float4 acc1 = make_float4(0.f, 0.f, 0.f, 0.f);

    if (c0 < D && r0 < r1) {
        const float* base = hs + (start + (long long)r0) * (long long)D + c0;
        const long long stride = D;
        int r = r0;
        for (; r + 7 < r1; r += 8) {     // MLP=8 independent LDG.128
            float4 v0 = ldcs4(base);
            float4 v1 = ldcs4(base + stride);
            float4 v2 = ldcs4(base + 2 * stride);
            float4 v3 = ldcs4(base + 3 * stride);
            float4 v4 = ldcs4(base + 4 * stride);
            float4 v5 = ldcs4(base + 5 * stride);
            float4 v6 = ldcs4(base + 6 * stride);
            float4 v7 = ldcs4(base + 7 * stride);
            acc0.x += v0.x + v1.x + v2.x + v3.x;
            acc0.y += v0.y + v1.y + v2.y + v3.y;
            acc0.z += v0.z + v1.z + v2.z + v3.z;
            acc0.w += v0.w + v1.w + v2.w + v3.w;
            acc1.x += v4.x + v5.x + v6.x + v7.x;
            acc1.y += v4.y + v5.y + v6.y + v7.y;
            acc1.z += v4.z + v5.z + v6.z + v7.z;
            acc1.w += v4.w + v5.w + v6.w + v7.w;
            base += 8 * stride;
        }
        for (; r < r1; r++) {
            float4 v = ldcs4(base);
            acc0.x += v.x; acc0.y += v.y; acc0.z += v.z; acc0.w += v.w;
            base += stride;
        }
    }

    if (c0 < D) {
        acc0.x += acc1.x; acc0.y += acc1.y; acc0.z += acc1.z; acc0.w += acc1.w;
        float* p = &g_part[((size_t)split * B + b) * (size_t)D + c0];
        *(float4*)p = acc0;
    }
}

// ---------------------------------------------------------------------------
// Kernel 2 (fused, PDL): reduce TSPLIT partials -> mean -> L2 normalize.
// One block per sequence; blockDim.x == D/4 (one float4 per thread, D<=4096).
// cudaGridDependencySynchronize() gates the data-dependent reads so the
// kernel's launch/prologue overlaps kernel 1's tail.
// ---------------------------------------------------------------------------
__global__ __launch_bounds__(1024)
void mean_norm_kernel(const int* __restrict__ plen,
                      const int* __restrict__ ilen,
                      float* __restrict__ out,
                      int B, int D)
{
    const int b = blockIdx.x;
    const int c = threadIdx.x * 4;   // float4 column owned by this thread

    // Wait for the upstream (pool_partial_kernel) grid to complete.
    cudaGridDependencySynchronize();

    float4 s = make_float4(0.f, 0.f, 0.f, 0.f);
    if (c < D) {
#pragma unroll
        for (int t = 0; t < TSPLIT; t++) {
            const float4 v = *(const float4*)&g_part[((size_t)t * B + b) * (size_t)D + c];
            s.x += v.x; s.y += v.y; s.z += v.z; s.w += v.w;
        }
        const float inv = 1.0f / (float)(plen[b] - ilen[b]);
        s.x *= inv; s.y *= inv; s.z *= inv; s.w *= inv;
    }

    // block-reduce sum of squares of the mean vector
    float ss = s.x * s.x + s.y * s.y + s.z * s.z + s.w * s.w;
    __shared__ float sm[32];
    for (int off = 16; off > 0; off >>= 1)
        ss += __shfl_down_sync(0xFFFFFFFFu, ss, off);
    const int lane = threadIdx.x & 31, wid = threadIdx.x >> 5;
    if (lane == 0) sm[wid] = ss;
    __syncthreads();
    const int nwarps = (blockDim.x + 31) >> 5;
    if (wid == 0) {
        float v = (lane < nwarps) ? sm[lane] : 0.f;
        for (int off = 16; off > 0; off >>= 1)
            v += __shfl_down_sync(0xFFFFFFFFu, v, off);
        if (lane == 0) sm[0] = v;
    }
    __syncthreads();

    const float norm = fmaxf(sqrtf(sm[0]), 1e-12f);
    const float inv_n = 1.0f / norm;

    if (c < D) {
        s.x *= inv_n; s.y *= inv_n; s.z *= inv_n; s.w *= inv_n;
        *(float4*)(out + (size_t)b * D + c) = s;
    }
}

// ---------------------------------------------------------------------------
extern "C" void kernel_launch(void* const* d_in, const int* in_sizes, int n_in,
                              void* d_out, int out_size)
{
    const float* hs   = (const float*)d_in[0];
    const int*   plen = (const int*)d_in[1];
    const int*   ilen = (const int*)d_in[2];
    float*       out  = (float*)d_out;

    const int B = in_sizes[1];
    const int D = out_size / B;   // 4096

    // Stage 1: partial sums (memory-wall bound)
    dim3 grid1((D + 1023) / 1024, B, TSPLIT);
    pool_partial_kernel<<<grid1, 256>>>(hs, plen, ilen, B, D);

    // Stage 2: fused reduce + mean + L2 normalize, with programmatic
    // dependent launch so its prologue overlaps stage 1's tail.
    int threads = D / 4;            // 1024 for D=4096
    if (threads > 1024) threads = 1024;

    cudaLaunchConfig_t cfg = {};
    cfg.gridDim  = dim3(B, 1, 1);
    cfg.blockDim = dim3(threads, 1, 1);
    cfg.dynamicSmemBytes = 0;
    cfg.stream = 0;
    cudaLaunchAttribute attrs[1];
    attrs[0].id = cudaLaunchAttributeProgrammaticStreamSerialization;
    attrs[0].val.programmaticStreamSerializationAllowed = 1;
    cfg.attrs = attrs;
    cfg.numAttrs = 1;
    cudaLaunchKernelEx(&cfg, mean_norm_kernel, plen, ilen, out, B, D);
}